// round 1
// baseline (speedup 1.0000x reference)
#include <cuda_runtime.h>
#include <math.h>

#define N_ATOMS 10000
#define N_PAIRS 320000
#define CC 64

// ---------------- scratch (device globals; no allocation allowed) ----------------
__device__ float g_p1in[N_ATOMS * 64];      // tanh(tanh(p1@W1+b1)@W2+b2)
__device__ float g_v[N_ATOMS * 3];          // segment_sum(d3*fc, i)
__device__ float g_p1scat[N_ATOMS * 128];   // segment_sum(i_pair, i)
__device__ float g_p3acc[N_ATOMS * 192];    // segment_sum(ix, i)  [atom][3][64]

// ---------------- kernel 0: zero scratch ----------------
__global__ void zero_kernel() {
    int idx = blockIdx.x * blockDim.x + threadIdx.x;
    if (idx < N_ATOMS * 3)   g_v[idx] = 0.0f;
    if (idx < N_ATOMS * 128) g_p1scat[idx] = 0.0f;
    if (idx < N_ATOMS * 192) g_p3acc[idx] = 0.0f;
}

// ---------------- kernel 1: p1_in = tanh(tanh(p1@W1+b1)@W2+b2) ----------------
// grid 2500 blocks x 256 threads; 4 atoms per block (64 threads per atom)
__global__ void p1in_kernel(const float* __restrict__ p1,
                            const float* __restrict__ W1, const float* __restrict__ b1,
                            const float* __restrict__ W2, const float* __restrict__ b2) {
    __shared__ float W1s[4096], W2s[4096], b1s[64], b2s[64];
    __shared__ float xr[4 * 64], hs[4 * 64];
    int tid = threadIdx.x;
    for (int idx = tid; idx < 4096; idx += 256) { W1s[idx] = W1[idx]; W2s[idx] = W2[idx]; }
    if (tid < 64) { b1s[tid] = b1[tid]; b2s[tid] = b2[tid]; }
    int slot = tid >> 6, c = tid & 63;
    int a = blockIdx.x * 4 + slot;   // 10000 divisible by 4
    xr[slot * 64 + c] = p1[a * 64 + c];
    __syncthreads();
    float h = b1s[c];
    #pragma unroll 8
    for (int k = 0; k < 64; ++k) h += xr[slot * 64 + k] * W1s[k * 64 + c];
    hs[slot * 64 + c] = tanhf(h);
    __syncthreads();
    float o = b2s[c];
    #pragma unroll 8
    for (int k = 0; k < 64; ++k) o += hs[slot * 64 + k] * W2s[k * 64 + c];
    g_p1in[a * 64 + c] = tanhf(o);
}

// ---------------- kernel 2: v = segment_sum(d3*fc, i) ----------------
__global__ void vacc_kernel(const int* __restrict__ ind2,
                            const float* __restrict__ d3,
                            const float* __restrict__ fc) {
    int p = blockIdx.x * blockDim.x + threadIdx.x;
    if (p >= N_PAIRS) return;
    int i = ind2[2 * p];
    float f = fc[p];
    atomicAdd(&g_v[i * 3 + 0], d3[p * 3 + 0] * f);
    atomicAdd(&g_v[i * 3 + 1], d3[p * 3 + 1] * f);
    atomicAdd(&g_v[i * 3 + 2], d3[p * 3 + 2] * f);
}

// ---------------- kernel 3: main per-pair kernel ----------------
// 64 pairs/block, 256 threads. 5000 blocks.
// Dynamic smem layout (floats):
//   Xs   [0,        8256)   64x129  pair features (later reused as Z)
//   Ws   [8256,    20544)   128x96  weight tile (also iiW 64x128 = 8192)
//   sIp  [20544,   24704)   64x65   i_pair (pre-iiW, 64-dim per pair)
//   sB   [24704,   25344)   64x10   basis
//   sD3  [25344,   25536)   64x3
//   sFc  [25536,   25600)
//   sBias[25600,   25696)   8x12
//   sI/sJ[25696,   25824)   int x128
#define PAIR_SMEM_FLOATS 25824
__global__ void pair_kernel(const int* __restrict__ ind2,
                            const float* __restrict__ p3,
                            const float* __restrict__ basis,
                            const float* __restrict__ d3,
                            const float* __restrict__ fc,
                            const float* __restrict__ piW,
                            const float* __restrict__ pib,
                            const float* __restrict__ iiW) {
    extern __shared__ float sm[];
    float* Xs    = sm;
    float* Ws    = sm + 8256;
    float* sIp   = sm + 20544;
    float* sB    = sm + 24704;
    float* sD3   = sm + 25344;
    float* sFc   = sm + 25536;
    float* sBias = sm + 25600;
    int*   sI    = (int*)(sm + 25696);
    int*   sJ    = sI + 64;

    int tid = threadIdx.x;
    int pbase = blockIdx.x * 64;

    if (tid < 64) {
        sI[tid]  = ind2[2 * (pbase + tid)];
        sJ[tid]  = ind2[2 * (pbase + tid) + 1];
        sFc[tid] = fc[pbase + tid];
    }
    for (int idx = tid; idx < 192; idx += 256) sD3[idx] = d3[pbase * 3 + idx];
    for (int idx = tid; idx < 640; idx += 256) sB[idx]  = basis[pbase * 10 + idx];
    __syncthreads();
    // build Xs[m][k] = [p1in[i], p1in[j]]
    for (int idx = tid; idx < 8192; idx += 256) {
        int m = idx >> 7, k = idx & 127;
        float v = (k < 64) ? g_p1in[sI[m] * 64 + k] : g_p1in[sJ[m] * 64 + (k - 64)];
        Xs[m * 129 + k] = v;
    }

    int lane = tid & 31;
    int wg   = tid >> 5;   // warp id = basis c-group within chunk

    // ---- GEMM1: y = tanh(X @ piW + pib); i_pair[c] = sum_b y[c*10+b]*basis[b] ----
    for (int chunk = 0; chunk < 8; ++chunk) {
        __syncthreads();
        // stage W chunk: cols [chunk*80, chunk*80+80), padded 10->12 per group
        for (int idx = tid; idx < 10240; idx += 256) {
            int k = idx / 80, nl = idx % 80;
            Ws[k * 96 + (nl / 10) * 12 + (nl % 10)] = piW[k * 640 + chunk * 80 + nl];
        }
        if (tid < 80) sBias[(tid / 10) * 12 + (tid % 10)] = pib[chunk * 80 + tid];
        __syncthreads();

        float acc0[10], acc1[10];
        #pragma unroll
        for (int b = 0; b < 10; ++b) { acc0[b] = 0.0f; acc1[b] = 0.0f; }
        const float* xr0 = Xs + lane * 129;
        const float* xr1 = Xs + (lane + 32) * 129;
        #pragma unroll 4
        for (int k = 0; k < 128; ++k) {
            float a0 = xr0[k];
            float a1 = xr1[k];
            const float4* wp = (const float4*)(Ws + k * 96 + wg * 12);
            float4 w0 = wp[0], w1 = wp[1], w2 = wp[2];  // broadcast across warp
            float bv[10] = {w0.x, w0.y, w0.z, w0.w, w1.x, w1.y, w1.z, w1.w, w2.x, w2.y};
            #pragma unroll
            for (int b = 0; b < 10; ++b) { acc0[b] += a0 * bv[b]; acc1[b] += a1 * bv[b]; }
        }
        int c = chunk * 8 + wg;
        float ip0 = 0.0f, ip1 = 0.0f;
        #pragma unroll
        for (int b = 0; b < 10; ++b) {
            float bb = sBias[wg * 12 + b];
            ip0 += tanhf(acc0[b] + bb) * sB[lane * 10 + b];
            ip1 += tanhf(acc1[b] + bb) * sB[(lane + 32) * 10 + b];
        }
        sIp[lane * 65 + c]        = ip0;
        sIp[(lane + 32) * 65 + c] = ip1;
    }
    __syncthreads();

    // ---- stage 2: z = tanh(i_pair @ iiW)  (64 -> 128) ----
    for (int idx = tid; idx < 8192; idx += 256) Ws[idx] = iiW[idx];
    __syncthreads();
    {
        int n0 = wg * 16;
        float z0[16], z1[16];
        #pragma unroll
        for (int t = 0; t < 16; ++t) { z0[t] = 0.0f; z1[t] = 0.0f; }
        #pragma unroll 2
        for (int k = 0; k < 64; ++k) {
            float a0 = sIp[lane * 65 + k];
            float a1 = sIp[(lane + 32) * 65 + k];
            const float4* qp = (const float4*)(Ws + k * 128 + n0);
            float4 q0 = qp[0], q1 = qp[1], q2 = qp[2], q3 = qp[3];
            float bv[16] = {q0.x, q0.y, q0.z, q0.w, q1.x, q1.y, q1.z, q1.w,
                            q2.x, q2.y, q2.z, q2.w, q3.x, q3.y, q3.z, q3.w};
            #pragma unroll
            for (int t = 0; t < 16; ++t) { z0[t] += a0 * bv[t]; z1[t] += a1 * bv[t]; }
        }
        float* zr0 = Xs + lane * 129;        // Xs region reused as Z
        float* zr1 = Xs + (lane + 32) * 129;
        #pragma unroll
        for (int t = 0; t < 16; ++t) {
            zr0[n0 + t] = tanhf(z0[t]);
            zr1[n0 + t] = tanhf(z1[t]);
        }
    }
    __syncthreads();

    // ---- stage 3: scatter z into p1_scat[i]; geometry; scatter ix into p3acc[i] ----
    {
        int m = tid >> 2, q = tid & 3;     // 4 threads per pair
        int i = sI[m], j = sJ[m];
        float fcv = sFc[m];
        float dx = sD3[m * 3 + 0], dy = sD3[m * 3 + 1], dz = sD3[m * 3 + 2];
        float vx = g_v[i * 3 + 0], vy = g_v[i * 3 + 1], vz = g_v[i * 3 + 2];
        float proj = vx * dx + vy * dy + vz * dz;
        float wx = vx - proj * dx, wy = vy - proj * dy, wzc = vz - proj * dz;
        float w2 = wx * wx + wy * wy + wzc * wzc;
        float gdeg = w2 / (w2 + 1e-4f);            // (10*EPS)^2
        float rs = rsqrtf(w2 + 1e-6f);             // EPS^2
        float sc = rs * gdeg;
        float t3x = wx * sc, t3y = wy * sc, t3z = wzc * sc;
        float tb = gdeg * fcv * fcv;

        const float* zr = Xs + m * 129;
        float* ps = g_p1scat + (size_t)i * 128;
        #pragma unroll 8
        for (int t = 0; t < 32; ++t) atomicAdd(ps + q * 32 + t, zr[q * 32 + t]);

        const float* p3j = p3 + (size_t)j * 192;
        float* pa = g_p3acc + (size_t)i * 192;
        #pragma unroll 4
        for (int t = 0; t < 16; ++t) {
            int ccl = q * 16 + t;
            float g = zr[64 + ccl];                // i1b[c] (gate)
            float coef = g * tb;
            atomicAdd(pa + ccl,        p3j[ccl] * g        + dx * g + t3x * coef);
            atomicAdd(pa + 64 + ccl,   p3j[64 + ccl] * g   + dy * g + t3y * coef);
            atomicAdd(pa + 128 + ccl,  p3j[128 + ccl] * g  + dz * g + t3z * coef);
        }
    }
}

// ---------------- kernel 4: atom-side tail, writes d_out ----------------
// grid 148 x 256; each block handles 68 atoms, 4 concurrent (64 thr each)
#define FINAL_SMEM_FLOATS 36032
__global__ void atom_final_kernel(const float* __restrict__ postW1,
                                  const float* __restrict__ postW2,
                                  const float* __restrict__ eqW,
                                  const float* __restrict__ q1W,
                                  const float* __restrict__ q1b,
                                  const float* __restrict__ q2W,
                                  const float* __restrict__ q2b,
                                  float* __restrict__ out) {
    extern __shared__ float sm[];
    float* W1s  = sm;            // 8192  pp_post_W1 [128][64]
    float* W2s  = sm + 8192;     // 4096  pp_post_W2 [64][64]
    float* Es   = sm + 12288;    // 4096  eq_pp_W    [64][64]
    float* Q1s  = sm + 16384;    // 8192  pp1_W1     [128][64]
    float* Q2s  = sm + 24576;    // 8192  pp1_W2     [64][128]
    float* b1s  = sm + 32768;    // 64
    float* b2s  = sm + 32832;    // 128
    float* ps   = sm + 32960;    // 4x128
    float* p3a  = sm + 33472;    // 4x192
    float* sH   = sm + 34240;    // 4x64
    float* sP1  = sm + 34496;    // 4x64
    float* sP3n = sm + 34752;    // 4x192
    float* sD   = sm + 35520;    // 4x64
    float* sH2  = sm + 35776;    // 4x64

    int tid = threadIdx.x;
    for (int idx = tid; idx < 8192; idx += 256) W1s[idx] = postW1[idx];
    for (int idx = tid; idx < 4096; idx += 256) { W2s[idx] = postW2[idx]; Es[idx] = eqW[idx]; }
    for (int idx = tid; idx < 8192; idx += 256) { Q1s[idx] = q1W[idx]; Q2s[idx] = q2W[idx]; }
    if (tid < 64)  b1s[tid] = q1b[tid];
    if (tid < 128) b2s[tid] = q2b[tid];

    int slot = tid >> 6, c = tid & 63;
    int abase = blockIdx.x * 68;
    for (int it = 0; it < 17; ++it) {
        __syncthreads();
        int a = abase + it * 4 + slot;
        bool valid = (a < N_ATOMS);
        if (valid) {
            ps[slot * 128 + c]       = g_p1scat[a * 128 + c];
            ps[slot * 128 + 64 + c]  = g_p1scat[a * 128 + 64 + c];
            p3a[slot * 192 + c]       = g_p3acc[a * 192 + c];
            p3a[slot * 192 + 64 + c]  = g_p3acc[a * 192 + 64 + c];
            p3a[slot * 192 + 128 + c] = g_p3acc[a * 192 + 128 + c];
        } else {
            ps[slot * 128 + c] = 0.0f; ps[slot * 128 + 64 + c] = 0.0f;
            p3a[slot * 192 + c] = 0.0f; p3a[slot * 192 + 64 + c] = 0.0f;
            p3a[slot * 192 + 128 + c] = 0.0f;
        }
        __syncthreads();
        // h1 = tanh(p1_scat @ pp_post_W1)
        float h = 0.0f;
        #pragma unroll 8
        for (int k = 0; k < 128; ++k) h += ps[slot * 128 + k] * W1s[k * 64 + c];
        sH[slot * 64 + c] = tanhf(h);
        __syncthreads();
        // p1_new = tanh(h1 @ pp_post_W2); p3_new = p3acc @ eq; dotted
        float o = 0.0f;
        float p0 = 0.0f, p1v = 0.0f, p2 = 0.0f;
        #pragma unroll 8
        for (int k = 0; k < 64; ++k) {
            o += sH[slot * 64 + k] * W2s[k * 64 + c];
            float e = Es[k * 64 + c];
            p0  += p3a[slot * 192 + k]       * e;
            p1v += p3a[slot * 192 + 64 + k]  * e;
            p2  += p3a[slot * 192 + 128 + k] * e;
        }
        sP1[slot * 64 + c] = tanhf(o);
        sP3n[slot * 192 + c]       = p0;
        sP3n[slot * 192 + 64 + c]  = p1v;
        sP3n[slot * 192 + 128 + c] = p2;
        sD[slot * 64 + c] = p0 * p0 + p1v * p1v + p2 * p2;
        __syncthreads();
        // h2 = tanh([p1_new, dotted] @ pp1_W1 + b1)
        float h2 = b1s[c];
        #pragma unroll 8
        for (int k = 0; k < 64; ++k) {
            h2 += sP1[slot * 64 + k] * Q1s[k * 64 + c];
            h2 += sD[slot * 64 + k]  * Q1s[(64 + k) * 64 + c];
        }
        sH2[slot * 64 + c] = tanhf(h2);
        __syncthreads();
        // out = tanh(h2 @ pp1_W2 + b2); split g1/g3
        float o1 = b2s[c], o2 = b2s[64 + c];
        #pragma unroll 8
        for (int k = 0; k < 64; ++k) {
            float hh = sH2[slot * 64 + k];
            o1 += hh * Q2s[k * 128 + c];
            o2 += hh * Q2s[k * 128 + 64 + c];
        }
        o1 = tanhf(o1);
        o2 = tanhf(o2);
        if (valid) {
            out[a * 64 + c] = o1;                                    // p1_out
            float* po = out + N_ATOMS * 64 + (size_t)a * 192;        // p3_out
            po[c]        = sP3n[slot * 192 + c]       * o2;
            po[64 + c]   = sP3n[slot * 192 + 64 + c]  * o2;
            po[128 + c]  = sP3n[slot * 192 + 128 + c] * o2;
        }
    }
}

// ---------------- launch ----------------
extern "C" void kernel_launch(void* const* d_in, const int* in_sizes, int n_in,
                              void* d_out, int out_size) {
    const int*   ind2   = (const int*)d_in[0];
    const float* p1     = (const float*)d_in[1];
    const float* p3     = (const float*)d_in[2];
    const float* basis  = (const float*)d_in[3];
    const float* d3     = (const float*)d_in[4];
    const float* fc     = (const float*)d_in[5];
    const float* preW1  = (const float*)d_in[6];
    const float* preb1  = (const float*)d_in[7];
    const float* preW2  = (const float*)d_in[8];
    const float* preb2  = (const float*)d_in[9];
    const float* piW    = (const float*)d_in[10];
    const float* pib    = (const float*)d_in[11];
    const float* iiW    = (const float*)d_in[12];
    const float* postW1 = (const float*)d_in[13];
    const float* postW2 = (const float*)d_in[14];
    const float* eqW    = (const float*)d_in[15];
    const float* q1W    = (const float*)d_in[16];
    const float* q1b    = (const float*)d_in[17];
    const float* q2W    = (const float*)d_in[18];
    const float* q2b    = (const float*)d_in[19];
    float* out = (float*)d_out;

    cudaFuncSetAttribute(pair_kernel, cudaFuncAttributeMaxDynamicSharedMemorySize,
                         PAIR_SMEM_FLOATS * 4);
    cudaFuncSetAttribute(atom_final_kernel, cudaFuncAttributeMaxDynamicSharedMemorySize,
                         FINAL_SMEM_FLOATS * 4);

    zero_kernel<<<(N_ATOMS * 192 + 255) / 256, 256>>>();
    p1in_kernel<<<N_ATOMS / 4, 256>>>(p1, preW1, preb1, preW2, preb2);
    vacc_kernel<<<(N_PAIRS + 255) / 256, 256>>>(ind2, d3, fc);
    pair_kernel<<<N_PAIRS / 64, 256, PAIR_SMEM_FLOATS * 4>>>(ind2, p3, basis, d3, fc,
                                                             piW, pib, iiW);
    atom_final_kernel<<<148, 256, FINAL_SMEM_FLOATS * 4>>>(postW1, postW2, eqW,
                                                           q1W, q1b, q2W, q2b, out);
}

// round 2
// speedup vs baseline: 1.2489x; 1.2489x over previous
#include <cuda_runtime.h>
#include <math.h>

#define N_ATOMS 10000
#define N_PAIRS 320000
#define CC 64

typedef unsigned long long ull;

// ---------------- f32x2 helpers (Blackwell packed fp32) ----------------
__device__ __forceinline__ ull pack2(float x) {
    ull r; asm("mov.b64 %0, {%1, %1};" : "=l"(r) : "f"(x)); return r;
}
__device__ __forceinline__ void fma2(ull& acc, ull a, ull b) {
    asm("fma.rn.f32x2 %0, %1, %2, %0;" : "+l"(acc) : "l"(a), "l"(b));
}
__device__ __forceinline__ float2 unpack2(ull v) {
    float2 f; asm("mov.b64 {%0, %1}, %2;" : "=f"(f.x), "=f"(f.y) : "l"(v)); return f;
}
__device__ __forceinline__ float tanh_fast(float x) {
    float y; asm("tanh.approx.f32 %0, %1;" : "=f"(y) : "f"(x)); return y;
}

// ---------------- scratch (device globals; no allocation allowed) ----------------
__device__ float g_p1in[N_ATOMS * 64];      // tanh(tanh(p1@W1+b1)@W2+b2)
__device__ float g_v[N_ATOMS * 3];          // segment_sum(d3*fc, i)
__device__ float g_p1scat[N_ATOMS * 128];   // segment_sum(i_pair, i)
__device__ float g_p3acc[N_ATOMS * 192];    // segment_sum(ix, i)  [atom][3][64]

// ---------------- kernel 0: zero scratch ----------------
__global__ void zero_kernel() {
    int idx = blockIdx.x * blockDim.x + threadIdx.x;
    if (idx < N_ATOMS * 3)   g_v[idx] = 0.0f;
    if (idx < N_ATOMS * 128) g_p1scat[idx] = 0.0f;
    if (idx < N_ATOMS * 192) g_p3acc[idx] = 0.0f;
}

// ---------------- kernel 1: p1_in = tanh(tanh(p1@W1+b1)@W2+b2) ----------------
__global__ void p1in_kernel(const float* __restrict__ p1,
                            const float* __restrict__ W1, const float* __restrict__ b1,
                            const float* __restrict__ W2, const float* __restrict__ b2) {
    __shared__ float W1s[4096], W2s[4096], b1s[64], b2s[64];
    __shared__ float xr[4 * 64], hs[4 * 64];
    int tid = threadIdx.x;
    for (int idx = tid; idx < 4096; idx += 256) { W1s[idx] = W1[idx]; W2s[idx] = W2[idx]; }
    if (tid < 64) { b1s[tid] = b1[tid]; b2s[tid] = b2[tid]; }
    int slot = tid >> 6, c = tid & 63;
    int a = blockIdx.x * 4 + slot;
    xr[slot * 64 + c] = p1[a * 64 + c];
    __syncthreads();
    float h = b1s[c];
    #pragma unroll 8
    for (int k = 0; k < 64; ++k) h += xr[slot * 64 + k] * W1s[k * 64 + c];
    hs[slot * 64 + c] = tanhf(h);
    __syncthreads();
    float o = b2s[c];
    #pragma unroll 8
    for (int k = 0; k < 64; ++k) o += hs[slot * 64 + k] * W2s[k * 64 + c];
    g_p1in[a * 64 + c] = tanhf(o);
}

// ---------------- kernel 2: v = segment_sum(d3*fc, i) ----------------
__global__ void vacc_kernel(const int* __restrict__ ind2,
                            const float* __restrict__ d3,
                            const float* __restrict__ fc) {
    int p = blockIdx.x * blockDim.x + threadIdx.x;
    if (p >= N_PAIRS) return;
    int i = ind2[2 * p];
    float f = fc[p];
    atomicAdd(&g_v[i * 3 + 0], d3[p * 3 + 0] * f);
    atomicAdd(&g_v[i * 3 + 1], d3[p * 3 + 1] * f);
    atomicAdd(&g_v[i * 3 + 2], d3[p * 3 + 2] * f);
}

// ---------------- kernel 3: main per-pair kernel ----------------
// 64 pairs/block, 256 threads. 5000 blocks.
// smem layout (floats):
//   Xs   [0,        8256)   64x129  pair features (later reused as Z)
//   Ws   [8256,    20544)   128x96  weight tile (also iiW 64x128 = 8192)
//   sIp  [20544,   24704)   64x65   i_pair
//   sB   [24704,   25344)   64x10   basis
//   sD3  [25344,   25536)   64x3
//   sFc  [25536,   25600)
//   sBias[25600,   25696)   8x12
//   sI/sJ[25696,   25824)   int x128
#define PAIR_SMEM_FLOATS 25824
__global__ __launch_bounds__(256) void pair_kernel(
                            const int* __restrict__ ind2,
                            const float* __restrict__ p3,
                            const float* __restrict__ basis,
                            const float* __restrict__ d3,
                            const float* __restrict__ fc,
                            const float* __restrict__ piW,
                            const float* __restrict__ pib,
                            const float* __restrict__ iiW) {
    extern __shared__ float sm[];
    float* Xs    = sm;
    float* Ws    = sm + 8256;
    float* sIp   = sm + 20544;
    float* sB    = sm + 24704;
    float* sD3   = sm + 25344;
    float* sFc   = sm + 25536;
    float* sBias = sm + 25600;
    int*   sI    = (int*)(sm + 25696);
    int*   sJ    = sI + 64;

    int tid = threadIdx.x;
    int pbase = blockIdx.x * 64;

    if (tid < 64) {
        sI[tid]  = ind2[2 * (pbase + tid)];
        sJ[tid]  = ind2[2 * (pbase + tid) + 1];
        sFc[tid] = fc[pbase + tid];
    }
    for (int idx = tid; idx < 192; idx += 256) sD3[idx] = d3[pbase * 3 + idx];
    for (int idx = tid; idx < 640; idx += 256) sB[idx]  = basis[pbase * 10 + idx];
    __syncthreads();
    // build Xs[m][k] = [p1in[i], p1in[j]]
    for (int idx = tid; idx < 8192; idx += 256) {
        int m = idx >> 7, k = idx & 127;
        float v = (k < 64) ? g_p1in[sI[m] * 64 + k] : g_p1in[sJ[m] * 64 + (k - 64)];
        Xs[m * 129 + k] = v;
    }

    int lane = tid & 31;
    int wg   = tid >> 5;   // warp id = basis c-group within chunk

    // staging plan for W chunks: thread < 240 owns fixed column nl = tid%80,
    // covers k = tid/80 + 3*s  (3 k-strides of 80 threads).
    int s_nl = tid % 80;
    int s_k0 = tid / 80;                               // 0..2 for tid<240
    int s_dst = (s_nl / 10) * 12 + (s_nl % 10);        // fixed dst within row

    const float* xr0 = Xs + lane * 129;
    const float* xr1 = Xs + (lane + 32) * 129;

    // ---- GEMM1: y = tanh(X @ piW + pib); i_pair[c] = sum_b y[c*10+b]*basis[b] ----
    for (int chunk = 0; chunk < 8; ++chunk) {
        __syncthreads();
        if (tid < 240) {
            const float* src = piW + (size_t)s_k0 * 640 + chunk * 80 + s_nl;
            float* dst = Ws + s_k0 * 96 + s_dst;
            #pragma unroll 4
            for (int k = s_k0; k < 128; k += 3) {
                *dst = *src;
                src += 3 * 640;
                dst += 3 * 96;
            }
        }
        if (tid < 80) sBias[(tid / 10) * 12 + (tid % 10)] = pib[chunk * 80 + tid];
        __syncthreads();

        ull acc0[5], acc1[5];
        #pragma unroll
        for (int b = 0; b < 5; ++b) { acc0[b] = 0ULL; acc1[b] = 0ULL; }
        #pragma unroll 8
        for (int k = 0; k < 128; ++k) {
            ull A0 = pack2(xr0[k]);
            ull A1 = pack2(xr1[k]);
            const ull* wp = (const ull*)(Ws + k * 96 + wg * 12);   // 8B-aligned (wg*48B)
            ull w0 = wp[0], w1 = wp[1], w2 = wp[2], w3 = wp[3], w4 = wp[4];
            fma2(acc0[0], A0, w0); fma2(acc1[0], A1, w0);
            fma2(acc0[1], A0, w1); fma2(acc1[1], A1, w1);
            fma2(acc0[2], A0, w2); fma2(acc1[2], A1, w2);
            fma2(acc0[3], A0, w3); fma2(acc1[3], A1, w3);
            fma2(acc0[4], A0, w4); fma2(acc1[4], A1, w4);
        }
        int c = chunk * 8 + wg;
        float ip0 = 0.0f, ip1 = 0.0f;
        #pragma unroll
        for (int b = 0; b < 5; ++b) {
            float2 bb = *(const float2*)(sBias + wg * 12 + 2 * b);
            float2 t0 = unpack2(acc0[b]);
            float2 t1 = unpack2(acc1[b]);
            float2 bs0 = *(const float2*)(sB + lane * 10 + 2 * b);
            float2 bs1 = *(const float2*)(sB + (lane + 32) * 10 + 2 * b);
            ip0 += tanh_fast(t0.x + bb.x) * bs0.x + tanh_fast(t0.y + bb.y) * bs0.y;
            ip1 += tanh_fast(t1.x + bb.x) * bs1.x + tanh_fast(t1.y + bb.y) * bs1.y;
        }
        sIp[lane * 65 + c]        = ip0;
        sIp[(lane + 32) * 65 + c] = ip1;
    }
    __syncthreads();

    // ---- stage 2: z = tanh(i_pair @ iiW)  (64 -> 128) ----
    for (int idx = tid; idx < 8192; idx += 256) Ws[idx] = iiW[idx];
    __syncthreads();
    {
        int n0 = wg * 16;
        ull z0[8], z1[8];
        #pragma unroll
        for (int t = 0; t < 8; ++t) { z0[t] = 0ULL; z1[t] = 0ULL; }
        const float* ir0 = sIp + lane * 65;
        const float* ir1 = sIp + (lane + 32) * 65;
        #pragma unroll 4
        for (int k = 0; k < 64; ++k) {
            ull A0 = pack2(ir0[k]);
            ull A1 = pack2(ir1[k]);
            const ull* qp = (const ull*)(Ws + k * 128 + n0);       // 64B-aligned
            #pragma unroll
            for (int t = 0; t < 8; ++t) {
                ull w = qp[t];
                fma2(z0[t], A0, w);
                fma2(z1[t], A1, w);
            }
        }
        float* zr0 = Xs + lane * 129;        // Xs region reused as Z
        float* zr1 = Xs + (lane + 32) * 129;
        #pragma unroll
        for (int t = 0; t < 8; ++t) {
            float2 a = unpack2(z0[t]);
            float2 b = unpack2(z1[t]);
            zr0[n0 + 2 * t]     = tanh_fast(a.x);
            zr0[n0 + 2 * t + 1] = tanh_fast(a.y);
            zr1[n0 + 2 * t]     = tanh_fast(b.x);
            zr1[n0 + 2 * t + 1] = tanh_fast(b.y);
        }
    }
    __syncthreads();

    // ---- stage 3: scatter z into p1_scat[i]; geometry; scatter ix into p3acc[i] ----
    {
        int m = tid >> 2, q = tid & 3;     // 4 threads per pair
        int i = sI[m], j = sJ[m];
        float fcv = sFc[m];
        float dx = sD3[m * 3 + 0], dy = sD3[m * 3 + 1], dz = sD3[m * 3 + 2];
        float vx = g_v[i * 3 + 0], vy = g_v[i * 3 + 1], vz = g_v[i * 3 + 2];
        float proj = vx * dx + vy * dy + vz * dz;
        float wx = vx - proj * dx, wy = vy - proj * dy, wzc = vz - proj * dz;
        float w2 = wx * wx + wy * wy + wzc * wzc;
        float gdeg = w2 / (w2 + 1e-4f);            // (10*EPS)^2
        float rs = rsqrtf(w2 + 1e-6f);             // EPS^2
        float sc = rs * gdeg;
        float t3x = wx * sc, t3y = wy * sc, t3z = wzc * sc;
        float tb = gdeg * fcv * fcv;

        const float* zr = Xs + m * 129;
        float* ps = g_p1scat + (size_t)i * 128;
        #pragma unroll 8
        for (int t = 0; t < 32; ++t) atomicAdd(ps + q * 32 + t, zr[q * 32 + t]);

        const float* p3j = p3 + (size_t)j * 192;
        float* pa = g_p3acc + (size_t)i * 192;
        #pragma unroll 4
        for (int t = 0; t < 16; ++t) {
            int ccl = q * 16 + t;
            float g = zr[64 + ccl];                // i1b[c] (gate)
            float coef = g * tb;
            atomicAdd(pa + ccl,        p3j[ccl] * g        + dx * g + t3x * coef);
            atomicAdd(pa + 64 + ccl,   p3j[64 + ccl] * g   + dy * g + t3y * coef);
            atomicAdd(pa + 128 + ccl,  p3j[128 + ccl] * g  + dz * g + t3z * coef);
        }
    }
}

// ---------------- kernel 4: atom-side tail, writes d_out ----------------
#define FINAL_SMEM_FLOATS 36032
__global__ void atom_final_kernel(const float* __restrict__ postW1,
                                  const float* __restrict__ postW2,
                                  const float* __restrict__ eqW,
                                  const float* __restrict__ q1W,
                                  const float* __restrict__ q1b,
                                  const float* __restrict__ q2W,
                                  const float* __restrict__ q2b,
                                  float* __restrict__ out) {
    extern __shared__ float sm[];
    float* W1s  = sm;            // 8192
    float* W2s  = sm + 8192;     // 4096
    float* Es   = sm + 12288;    // 4096
    float* Q1s  = sm + 16384;    // 8192
    float* Q2s  = sm + 24576;    // 8192
    float* b1s  = sm + 32768;    // 64
    float* b2s  = sm + 32832;    // 128
    float* ps   = sm + 32960;    // 4x128
    float* p3a  = sm + 33472;    // 4x192
    float* sH   = sm + 34240;    // 4x64
    float* sP1  = sm + 34496;    // 4x64
    float* sP3n = sm + 34752;    // 4x192
    float* sD   = sm + 35520;    // 4x64
    float* sH2  = sm + 35776;    // 4x64

    int tid = threadIdx.x;
    for (int idx = tid; idx < 8192; idx += 256) W1s[idx] = postW1[idx];
    for (int idx = tid; idx < 4096; idx += 256) { W2s[idx] = postW2[idx]; Es[idx] = eqW[idx]; }
    for (int idx = tid; idx < 8192; idx += 256) { Q1s[idx] = q1W[idx]; Q2s[idx] = q2W[idx]; }
    if (tid < 64)  b1s[tid] = q1b[tid];
    if (tid < 128) b2s[tid] = q2b[tid];

    int slot = tid >> 6, c = tid & 63;
    int abase = blockIdx.x * 68;
    for (int it = 0; it < 17; ++it) {
        __syncthreads();
        int a = abase + it * 4 + slot;
        bool valid = (a < N_ATOMS);
        if (valid) {
            ps[slot * 128 + c]       = g_p1scat[a * 128 + c];
            ps[slot * 128 + 64 + c]  = g_p1scat[a * 128 + 64 + c];
            p3a[slot * 192 + c]       = g_p3acc[a * 192 + c];
            p3a[slot * 192 + 64 + c]  = g_p3acc[a * 192 + 64 + c];
            p3a[slot * 192 + 128 + c] = g_p3acc[a * 192 + 128 + c];
        } else {
            ps[slot * 128 + c] = 0.0f; ps[slot * 128 + 64 + c] = 0.0f;
            p3a[slot * 192 + c] = 0.0f; p3a[slot * 192 + 64 + c] = 0.0f;
            p3a[slot * 192 + 128 + c] = 0.0f;
        }
        __syncthreads();
        float h = 0.0f;
        #pragma unroll 8
        for (int k = 0; k < 128; ++k) h += ps[slot * 128 + k] * W1s[k * 64 + c];
        sH[slot * 64 + c] = tanhf(h);
        __syncthreads();
        float o = 0.0f;
        float p0 = 0.0f, p1v = 0.0f, p2 = 0.0f;
        #pragma unroll 8
        for (int k = 0; k < 64; ++k) {
            o += sH[slot * 64 + k] * W2s[k * 64 + c];
            float e = Es[k * 64 + c];
            p0  += p3a[slot * 192 + k]       * e;
            p1v += p3a[slot * 192 + 64 + k]  * e;
            p2  += p3a[slot * 192 + 128 + k] * e;
        }
        sP1[slot * 64 + c] = tanhf(o);
        sP3n[slot * 192 + c]       = p0;
        sP3n[slot * 192 + 64 + c]  = p1v;
        sP3n[slot * 192 + 128 + c] = p2;
        sD[slot * 64 + c] = p0 * p0 + p1v * p1v + p2 * p2;
        __syncthreads();
        float h2 = b1s[c];
        #pragma unroll 8
        for (int k = 0; k < 64; ++k) {
            h2 += sP1[slot * 64 + k] * Q1s[k * 64 + c];
            h2 += sD[slot * 64 + k]  * Q1s[(64 + k) * 64 + c];
        }
        sH2[slot * 64 + c] = tanhf(h2);
        __syncthreads();
        float o1 = b2s[c], o2 = b2s[64 + c];
        #pragma unroll 8
        for (int k = 0; k < 64; ++k) {
            float hh = sH2[slot * 64 + k];
            o1 += hh * Q2s[k * 128 + c];
            o2 += hh * Q2s[k * 128 + 64 + c];
        }
        o1 = tanhf(o1);
        o2 = tanhf(o2);
        if (valid) {
            out[a * 64 + c] = o1;
            float* po = out + N_ATOMS * 64 + (size_t)a * 192;
            po[c]        = sP3n[slot * 192 + c]       * o2;
            po[64 + c]   = sP3n[slot * 192 + 64 + c]  * o2;
            po[128 + c]  = sP3n[slot * 192 + 128 + c] * o2;
        }
    }
}

// ---------------- launch ----------------
extern "C" void kernel_launch(void* const* d_in, const int* in_sizes, int n_in,
                              void* d_out, int out_size) {
    const int*   ind2   = (const int*)d_in[0];
    const float* p1     = (const float*)d_in[1];
    const float* p3     = (const float*)d_in[2];
    const float* basis  = (const float*)d_in[3];
    const float* d3     = (const float*)d_in[4];
    const float* fc     = (const float*)d_in[5];
    const float* preW1  = (const float*)d_in[6];
    const float* preb1  = (const float*)d_in[7];
    const float* preW2  = (const float*)d_in[8];
    const float* preb2  = (const float*)d_in[9];
    const float* piW    = (const float*)d_in[10];
    const float* pib    = (const float*)d_in[11];
    const float* iiW    = (const float*)d_in[12];
    const float* postW1 = (const float*)d_in[13];
    const float* postW2 = (const float*)d_in[14];
    const float* eqW    = (const float*)d_in[15];
    const float* q1W    = (const float*)d_in[16];
    const float* q1b    = (const float*)d_in[17];
    const float* q2W    = (const float*)d_in[18];
    const float* q2b    = (const float*)d_in[19];
    float* out = (float*)d_out;

    cudaFuncSetAttribute(pair_kernel, cudaFuncAttributeMaxDynamicSharedMemorySize,
                         PAIR_SMEM_FLOATS * 4);
    cudaFuncSetAttribute(atom_final_kernel, cudaFuncAttributeMaxDynamicSharedMemorySize,
                         FINAL_SMEM_FLOATS * 4);

    zero_kernel<<<(N_ATOMS * 192 + 255) / 256, 256>>>();
    p1in_kernel<<<N_ATOMS / 4, 256>>>(p1, preW1, preb1, preW2, preb2);
    vacc_kernel<<<(N_PAIRS + 255) / 256, 256>>>(ind2, d3, fc);
    pair_kernel<<<N_PAIRS / 64, 256, PAIR_SMEM_FLOATS * 4>>>(ind2, p3, basis, d3, fc,
                                                             piW, pib, iiW);
    atom_final_kernel<<<148, 256, FINAL_SMEM_FLOATS * 4>>>(postW1, postW2, eqW,
                                                           q1W, q1b, q2W, q2b, out);
}

// round 4
// speedup vs baseline: 1.4980x; 1.1995x over previous
#include <cuda_runtime.h>
#include <math.h>

#define N_ATOMS 10000
#define N_PAIRS 320000
#define CC 64

typedef unsigned long long ull;

// ---------------- f32x2 helpers (Blackwell packed fp32) ----------------
__device__ __forceinline__ ull pack2(float x) {
    ull r; asm("mov.b64 %0, {%1, %1};" : "=l"(r) : "f"(x)); return r;
}
__device__ __forceinline__ void fma2(ull& acc, ull a, ull b) {
    asm("fma.rn.f32x2 %0, %1, %2, %0;" : "+l"(acc) : "l"(a), "l"(b));
}
__device__ __forceinline__ float2 unpack2(ull v) {
    float2 f; asm("mov.b64 {%0, %1}, %2;" : "=f"(f.x), "=f"(f.y) : "l"(v)); return f;
}
__device__ __forceinline__ float tanh_fast(float x) {
    float y; asm("tanh.approx.f32 %0, %1;" : "=f"(y) : "f"(x)); return y;
}

// ---------------- scratch (device globals; no allocation allowed) ----------------
__device__ float g_p1in[N_ATOMS * 64];
__device__ float g_v[N_ATOMS * 3];
__device__ float g_p1scat[N_ATOMS * 128];
__device__ float g_p3acc[N_ATOMS * 192];
__device__ ull   g_piWT[5 * 128 * 64];   // [bpair][k][c] packed (b=2bp, 2bp+1)
__device__ ull   g_pibT[5 * 64];         // [bpair][c]

// ---------------- kernel 0: zero scratch ----------------
__global__ void zero_kernel() {
    int idx = blockIdx.x * blockDim.x + threadIdx.x;
    if (idx < N_ATOMS * 3)   g_v[idx] = 0.0f;
    if (idx < N_ATOMS * 128) g_p1scat[idx] = 0.0f;
    if (idx < N_ATOMS * 192) g_p3acc[idx] = 0.0f;
}

// ---------------- kernel 0b: pre-transpose piW / pib into packed-b layout ----------------
__global__ void prep_kernel(const float* __restrict__ piW, const float* __restrict__ pib) {
    int idx = blockIdx.x * blockDim.x + threadIdx.x;
    if (idx < 5 * 128 * 64) {
        int c  = idx & 63;
        int k  = (idx >> 6) & 127;
        int bp = idx >> 13;
        float lo = piW[k * 640 + c * 10 + 2 * bp];
        float hi = piW[k * 640 + c * 10 + 2 * bp + 1];
        uint2 u; u.x = __float_as_uint(lo); u.y = __float_as_uint(hi);
        g_piWT[idx] = *(ull*)&u;
    }
    if (idx < 320) {
        int c  = idx & 63;
        int bp = idx >> 6;
        float lo = pib[c * 10 + 2 * bp];
        float hi = pib[c * 10 + 2 * bp + 1];
        uint2 u; u.x = __float_as_uint(lo); u.y = __float_as_uint(hi);
        g_pibT[idx] = *(ull*)&u;
    }
}

// ---------------- kernel 1: p1_in = tanh(tanh(p1@W1+b1)@W2+b2) ----------------
__global__ void p1in_kernel(const float* __restrict__ p1,
                            const float* __restrict__ W1, const float* __restrict__ b1,
                            const float* __restrict__ W2, const float* __restrict__ b2) {
    __shared__ float W1s[4096], W2s[4096], b1s[64], b2s[64];
    __shared__ float xr[4 * 64], hs[4 * 64];
    int tid = threadIdx.x;
    for (int idx = tid; idx < 4096; idx += 256) { W1s[idx] = W1[idx]; W2s[idx] = W2[idx]; }
    if (tid < 64) { b1s[tid] = b1[tid]; b2s[tid] = b2[tid]; }
    int slot = tid >> 6, c = tid & 63;
    int a = blockIdx.x * 4 + slot;
    xr[slot * 64 + c] = p1[a * 64 + c];
    __syncthreads();
    float h = b1s[c];
    #pragma unroll 8
    for (int k = 0; k < 64; ++k) h += xr[slot * 64 + k] * W1s[k * 64 + c];
    hs[slot * 64 + c] = tanhf(h);
    __syncthreads();
    float o = b2s[c];
    #pragma unroll 8
    for (int k = 0; k < 64; ++k) o += hs[slot * 64 + k] * W2s[k * 64 + c];
    g_p1in[a * 64 + c] = tanhf(o);
}

// ---------------- kernel 2: v = segment_sum(d3*fc, i) ----------------
__global__ void vacc_kernel(const int* __restrict__ ind2,
                            const float* __restrict__ d3,
                            const float* __restrict__ fc) {
    int p = blockIdx.x * blockDim.x + threadIdx.x;
    if (p >= N_PAIRS) return;
    int i = ind2[2 * p];
    float f = fc[p];
    atomicAdd(&g_v[i * 3 + 0], d3[p * 3 + 0] * f);
    atomicAdd(&g_v[i * 3 + 1], d3[p * 3 + 1] * f);
    atomicAdd(&g_v[i * 3 + 2], d3[p * 3 + 2] * f);
}

// ---------------- kernel 3: main per-pair kernel ----------------
// 64 pairs/block, 256 threads (8 warps), 5000 blocks.
// smem regions (floats):
//   RegA [0,     10240)  : Xs 64x129 gather  -> W'' chunk (5120 ull) -> iiW (8192)
//   RegB [10240, 18496)  : Xt 128x64 (transposed X) -> Z 64x129
//   sIp  [18496, 22656)  : 64x65 i_pair
//   sB   [22656, 23296)  : basis 64x10
//   sPib [23296, 23936)  : bias pairs (320 ull)
//   sD3  [23936, 24128)  sFc [24128, 24192)  sI/sJ [24192, 24320)
#define PAIR_SMEM_FLOATS 24320
__global__ __launch_bounds__(256, 2) void pair_kernel(
                            const int* __restrict__ ind2,
                            const float* __restrict__ p3,
                            const float* __restrict__ basis,
                            const float* __restrict__ d3,
                            const float* __restrict__ fc,
                            const float* __restrict__ iiW) {
    extern __shared__ float sm[];
    float* RegA  = sm;
    float* RegB  = sm + 10240;
    float* sIp   = sm + 18496;
    float* sB    = sm + 22656;
    ull*   sPibU = (ull*)(sm + 23296);
    float* sD3   = sm + 23936;
    float* sFc   = sm + 24128;
    int*   sI    = (int*)(sm + 24192);
    int*   sJ    = sI + 64;

    int tid = threadIdx.x;
    int lane = tid & 31;
    int wg   = tid >> 5;
    int pbase = blockIdx.x * 64;

    if (tid < 64) {
        sI[tid]  = ind2[2 * (pbase + tid)];
        sJ[tid]  = ind2[2 * (pbase + tid) + 1];
        sFc[tid] = fc[pbase + tid];
    }
    for (int idx = tid; idx < 192; idx += 256) sD3[idx] = d3[pbase * 3 + idx];
    for (int idx = tid; idx < 640; idx += 256) sB[idx]  = basis[pbase * 10 + idx];
    // FIX (R3 bug): 320 entries but only 256 threads -> must loop, not predicate
    for (int idx = tid; idx < 320; idx += 256) sPibU[idx] = g_pibT[idx];
    __syncthreads();

    // gather Xs[m][k] = [p1in[i], p1in[j]]  (RegA, stride 129)
    for (int idx = tid; idx < 8192; idx += 256) {
        int m = idx >> 7, k = idx & 127;
        float v = (k < 64) ? g_p1in[sI[m] * 64 + k] : g_p1in[sJ[m] * 64 + (k - 64)];
        RegA[m * 129 + k] = v;
    }
    __syncthreads();

    // transpose -> Xt[k][m] (RegB, stride 64); both sides conflict-free
    for (int idx = tid; idx < 8192; idx += 256) {
        int m = idx & 63, k = idx >> 6;
        RegB[k * 64 + m] = RegA[m * 129 + k];
    }
    // (kc-loop's leading sync protects RegA overwrite and RegB reads)

    // ---- GEMM1: lane = channel c, warp = 8 rows; W'' staged per (cg, kc) ----
    ull* WsU = (ull*)RegA;
    const float4* srcW = (const float4*)g_piWT;
    float4* dstW = (float4*)RegA;
    const float* xrow = RegB + wg * 8;

    for (int cg = 0; cg < 2; ++cg) {
        ull acc[8][5];
        #pragma unroll
        for (int r = 0; r < 8; ++r)
            #pragma unroll
            for (int bp = 0; bp < 5; ++bp) acc[r][bp] = 0ULL;

        for (int kc = 0; kc < 4; ++kc) {
            __syncthreads();
            // stage 5120 ull = 2560 float4 : [bp][kl][cl] chunk, coalesced both ways
            {
                int kbase = kc * 32;
                for (int idx = tid; idx < 2560; idx += 256) {
                    int cl2 = idx & 15;
                    int kl  = (idx >> 4) & 31;
                    int bp  = idx >> 9;
                    dstW[(bp * 32 + kl) * 16 + cl2] =
                        srcW[bp * 4096 + (kbase + kl) * 32 + cg * 16 + cl2];
                }
            }
            __syncthreads();

            const float* xk = xrow + kc * 32 * 64;
            #pragma unroll 4
            for (int kl = 0; kl < 32; ++kl) {
                float4 a04 = *(const float4*)(xk + kl * 64);
                float4 a14 = *(const float4*)(xk + kl * 64 + 4);
                ull A0 = pack2(a04.x), A1 = pack2(a04.y), A2 = pack2(a04.z), A3 = pack2(a04.w);
                ull A4 = pack2(a14.x), A5 = pack2(a14.y), A6 = pack2(a14.z), A7 = pack2(a14.w);
                ull w[5];
                #pragma unroll
                for (int bp = 0; bp < 5; ++bp) w[bp] = WsU[bp * 1024 + kl * 32 + lane];
                #pragma unroll
                for (int bp = 0; bp < 5; ++bp) {
                    fma2(acc[0][bp], A0, w[bp]);
                    fma2(acc[1][bp], A1, w[bp]);
                    fma2(acc[2][bp], A2, w[bp]);
                    fma2(acc[3][bp], A3, w[bp]);
                    fma2(acc[4][bp], A4, w[bp]);
                    fma2(acc[5][bp], A5, w[bp]);
                    fma2(acc[6][bp], A6, w[bp]);
                    fma2(acc[7][bp], A7, w[bp]);
                }
            }
        }
        // epilogue: tanh + basis contraction -> i_pair[m][c]
        int c = cg * 32 + lane;
        #pragma unroll
        for (int r = 0; r < 8; ++r) {
            int m = wg * 8 + r;
            float s = 0.0f;
            #pragma unroll
            for (int bp = 0; bp < 5; ++bp) {
                float2 t  = unpack2(acc[r][bp]);
                float2 bb = unpack2(sPibU[bp * 64 + c]);
                float2 bs = *(const float2*)(sB + m * 10 + 2 * bp);
                s += tanh_fast(t.x + bb.x) * bs.x + tanh_fast(t.y + bb.y) * bs.y;
            }
            sIp[m * 65 + c] = s;
        }
    }
    __syncthreads();

    // ---- stage 2: z = tanh(i_pair @ iiW)  (64 -> 128), Z into RegB (stride 129) ----
    for (int idx = tid; idx < 8192; idx += 256) RegA[idx] = iiW[idx];
    __syncthreads();
    {
        int n0 = wg * 16;
        ull z0[8], z1[8];
        #pragma unroll
        for (int t = 0; t < 8; ++t) { z0[t] = 0ULL; z1[t] = 0ULL; }
        const float* ir0 = sIp + lane * 65;
        const float* ir1 = sIp + (lane + 32) * 65;
        #pragma unroll 4
        for (int k = 0; k < 64; ++k) {
            ull A0 = pack2(ir0[k]);
            ull A1 = pack2(ir1[k]);
            const ull* qp = (const ull*)(RegA + k * 128 + n0);
            #pragma unroll
            for (int t = 0; t < 8; ++t) {
                ull w = qp[t];
                fma2(z0[t], A0, w);
                fma2(z1[t], A1, w);
            }
        }
        float* zr0 = RegB + lane * 129;
        float* zr1 = RegB + (lane + 32) * 129;
        #pragma unroll
        for (int t = 0; t < 8; ++t) {
            float2 a = unpack2(z0[t]);
            float2 b = unpack2(z1[t]);
            zr0[n0 + 2 * t]     = tanh_fast(a.x);
            zr0[n0 + 2 * t + 1] = tanh_fast(a.y);
            zr1[n0 + 2 * t]     = tanh_fast(b.x);
            zr1[n0 + 2 * t + 1] = tanh_fast(b.y);
        }
    }
    __syncthreads();

    // ---- stage 3: scatter z; geometry; scatter ix ----
    {
        int m = tid >> 2, q = tid & 3;
        int i = sI[m], j = sJ[m];
        float fcv = sFc[m];
        float dx = sD3[m * 3 + 0], dy = sD3[m * 3 + 1], dz = sD3[m * 3 + 2];
        float vx = g_v[i * 3 + 0], vy = g_v[i * 3 + 1], vz = g_v[i * 3 + 2];
        float proj = vx * dx + vy * dy + vz * dz;
        float wx = vx - proj * dx, wy = vy - proj * dy, wzc = vz - proj * dz;
        float w2 = wx * wx + wy * wy + wzc * wzc;
        float gdeg = w2 / (w2 + 1e-4f);
        float rs = rsqrtf(w2 + 1e-6f);
        float sc = rs * gdeg;
        float t3x = wx * sc, t3y = wy * sc, t3z = wzc * sc;
        float tb = gdeg * fcv * fcv;

        const float* zr = RegB + m * 129;
        float* ps = g_p1scat + (size_t)i * 128;
        #pragma unroll 8
        for (int t = 0; t < 32; ++t) atomicAdd(ps + q * 32 + t, zr[q * 32 + t]);

        const float* p3j = p3 + (size_t)j * 192;
        float* pa = g_p3acc + (size_t)i * 192;
        #pragma unroll 4
        for (int t = 0; t < 16; ++t) {
            int ccl = q * 16 + t;
            float g = zr[64 + ccl];
            float coef = g * tb;
            atomicAdd(pa + ccl,        p3j[ccl] * g        + dx * g + t3x * coef);
            atomicAdd(pa + 64 + ccl,   p3j[64 + ccl] * g   + dy * g + t3y * coef);
            atomicAdd(pa + 128 + ccl,  p3j[128 + ccl] * g  + dz * g + t3z * coef);
        }
    }
}

// ---------------- kernel 4: atom-side tail, writes d_out ----------------
#define FINAL_SMEM_FLOATS 36032
__global__ void atom_final_kernel(const float* __restrict__ postW1,
                                  const float* __restrict__ postW2,
                                  const float* __restrict__ eqW,
                                  const float* __restrict__ q1W,
                                  const float* __restrict__ q1b,
                                  const float* __restrict__ q2W,
                                  const float* __restrict__ q2b,
                                  float* __restrict__ out) {
    extern __shared__ float sm[];
    float* W1s  = sm;
    float* W2s  = sm + 8192;
    float* Es   = sm + 12288;
    float* Q1s  = sm + 16384;
    float* Q2s  = sm + 24576;
    float* b1s  = sm + 32768;
    float* b2s  = sm + 32832;
    float* ps   = sm + 32960;
    float* p3a  = sm + 33472;
    float* sH   = sm + 34240;
    float* sP1  = sm + 34496;
    float* sP3n = sm + 34752;
    float* sD   = sm + 35520;
    float* sH2  = sm + 35776;

    int tid = threadIdx.x;
    for (int idx = tid; idx < 8192; idx += 256) W1s[idx] = postW1[idx];
    for (int idx = tid; idx < 4096; idx += 256) { W2s[idx] = postW2[idx]; Es[idx] = eqW[idx]; }
    for (int idx = tid; idx < 8192; idx += 256) { Q1s[idx] = q1W[idx]; Q2s[idx] = q2W[idx]; }
    if (tid < 64)  b1s[tid] = q1b[tid];
    if (tid < 128) b2s[tid] = q2b[tid];

    int slot = tid >> 6, c = tid & 63;
    int abase = blockIdx.x * 68;
    for (int it = 0; it < 17; ++it) {
        __syncthreads();
        int a = abase + it * 4 + slot;
        bool valid = (a < N_ATOMS);
        if (valid) {
            ps[slot * 128 + c]       = g_p1scat[a * 128 + c];
            ps[slot * 128 + 64 + c]  = g_p1scat[a * 128 + 64 + c];
            p3a[slot * 192 + c]       = g_p3acc[a * 192 + c];
            p3a[slot * 192 + 64 + c]  = g_p3acc[a * 192 + 64 + c];
            p3a[slot * 192 + 128 + c] = g_p3acc[a * 192 + 128 + c];
        } else {
            ps[slot * 128 + c] = 0.0f; ps[slot * 128 + 64 + c] = 0.0f;
            p3a[slot * 192 + c] = 0.0f; p3a[slot * 192 + 64 + c] = 0.0f;
            p3a[slot * 192 + 128 + c] = 0.0f;
        }
        __syncthreads();
        float h = 0.0f;
        #pragma unroll 8
        for (int k = 0; k < 128; ++k) h += ps[slot * 128 + k] * W1s[k * 64 + c];
        sH[slot * 64 + c] = tanhf(h);
        __syncthreads();
        float o = 0.0f;
        float p0 = 0.0f, p1v = 0.0f, p2 = 0.0f;
        #pragma unroll 8
        for (int k = 0; k < 64; ++k) {
            o += sH[slot * 64 + k] * W2s[k * 64 + c];
            float e = Es[k * 64 + c];
            p0  += p3a[slot * 192 + k]       * e;
            p1v += p3a[slot * 192 + 64 + k]  * e;
            p2  += p3a[slot * 192 + 128 + k] * e;
        }
        sP1[slot * 64 + c] = tanhf(o);
        sP3n[slot * 192 + c]       = p0;
        sP3n[slot * 192 + 64 + c]  = p1v;
        sP3n[slot * 192 + 128 + c] = p2;
        sD[slot * 64 + c] = p0 * p0 + p1v * p1v + p2 * p2;
        __syncthreads();
        float h2 = b1s[c];
        #pragma unroll 8
        for (int k = 0; k < 64; ++k) {
            h2 += sP1[slot * 64 + k] * Q1s[k * 64 + c];
            h2 += sD[slot * 64 + k]  * Q1s[(64 + k) * 64 + c];
        }
        sH2[slot * 64 + c] = tanhf(h2);
        __syncthreads();
        float o1 = b2s[c], o2 = b2s[64 + c];
        #pragma unroll 8
        for (int k = 0; k < 64; ++k) {
            float hh = sH2[slot * 64 + k];
            o1 += hh * Q2s[k * 128 + c];
            o2 += hh * Q2s[k * 128 + 64 + c];
        }
        o1 = tanhf(o1);
        o2 = tanhf(o2);
        if (valid) {
            out[a * 64 + c] = o1;
            float* po = out + N_ATOMS * 64 + (size_t)a * 192;
            po[c]        = sP3n[slot * 192 + c]       * o2;
            po[64 + c]   = sP3n[slot * 192 + 64 + c]  * o2;
            po[128 + c]  = sP3n[slot * 192 + 128 + c] * o2;
        }
    }
}

// ---------------- launch ----------------
extern "C" void kernel_launch(void* const* d_in, const int* in_sizes, int n_in,
                              void* d_out, int out_size) {
    const int*   ind2   = (const int*)d_in[0];
    const float* p1     = (const float*)d_in[1];
    const float* p3     = (const float*)d_in[2];
    const float* basis  = (const float*)d_in[3];
    const float* d3     = (const float*)d_in[4];
    const float* fc     = (const float*)d_in[5];
    const float* preW1  = (const float*)d_in[6];
    const float* preb1  = (const float*)d_in[7];
    const float* preW2  = (const float*)d_in[8];
    const float* preb2  = (const float*)d_in[9];
    const float* piW    = (const float*)d_in[10];
    const float* pib    = (const float*)d_in[11];
    const float* iiW    = (const float*)d_in[12];
    const float* postW1 = (const float*)d_in[13];
    const float* postW2 = (const float*)d_in[14];
    const float* eqW    = (const float*)d_in[15];
    const float* q1W    = (const float*)d_in[16];
    const float* q1b    = (const float*)d_in[17];
    const float* q2W    = (const float*)d_in[18];
    const float* q2b    = (const float*)d_in[19];
    float* out = (float*)d_out;

    cudaFuncSetAttribute(pair_kernel, cudaFuncAttributeMaxDynamicSharedMemorySize,
                         PAIR_SMEM_FLOATS * 4);
    cudaFuncSetAttribute(atom_final_kernel, cudaFuncAttributeMaxDynamicSharedMemorySize,
                         FINAL_SMEM_FLOATS * 4);

    zero_kernel<<<(N_ATOMS * 192 + 255) / 256, 256>>>();
    prep_kernel<<<(5 * 128 * 64 + 255) / 256, 256>>>(piW, pib);
    p1in_kernel<<<N_ATOMS / 4, 256>>>(p1, preW1, preb1, preW2, preb2);
    vacc_kernel<<<(N_PAIRS + 255) / 256, 256>>>(ind2, d3, fc);
    pair_kernel<<<N_PAIRS / 64, 256, PAIR_SMEM_FLOATS * 4>>>(ind2, p3, basis, d3, fc, iiW);
    atom_final_kernel<<<148, 256, FINAL_SMEM_FLOATS * 4>>>(postW1, postW2, eqW,
                                                           q1W, q1b, q2W, q2b, out);
}

// round 5
// speedup vs baseline: 2.6347x; 1.7588x over previous
#include <cuda_runtime.h>
#include <math.h>

#define N_ATOMS 10000
#define N_PAIRS 320000
#define CC 64

typedef unsigned long long ull;

// ---------------- f32x2 helpers (Blackwell packed fp32) ----------------
__device__ __forceinline__ ull pack2(float x) {
    ull r; asm("mov.b64 %0, {%1, %1};" : "=l"(r) : "f"(x)); return r;
}
__device__ __forceinline__ void fma2(ull& acc, ull a, ull b) {
    asm("fma.rn.f32x2 %0, %1, %2, %0;" : "+l"(acc) : "l"(a), "l"(b));
}
__device__ __forceinline__ float2 unpack2(ull v) {
    float2 f; asm("mov.b64 {%0, %1}, %2;" : "=f"(f.x), "=f"(f.y) : "l"(v)); return f;
}
__device__ __forceinline__ float tanh_fast(float x) {
    float y; asm("tanh.approx.f32 %0, %1;" : "=f"(y) : "f"(x)); return y;
}

// ---------------- scratch (device globals; no allocation allowed) ----------------
__device__ float g_p1in[N_ATOMS * 64];
__device__ float g_v[N_ATOMS * 3];
__device__ float g_p1scat[N_ATOMS * 128];
__device__ float g_p3acc[N_ATOMS * 192];
__device__ float g_piWn[2 * 10 * 64 * 64];   // [z][b][k][c]  (z=0 top half, 1 bottom)
__device__ float g_A[N_ATOMS * 640];         // p1in @ Wtop + pib   [atom][b][c]
__device__ float g_B[N_ATOMS * 640];         // p1in @ Wbot         [atom][b][c]

// ---------------- kernel 0: zero scratch ----------------
__global__ void zero_kernel() {
    int idx = blockIdx.x * blockDim.x + threadIdx.x;
    if (idx < N_ATOMS * 3)   g_v[idx] = 0.0f;
    if (idx < N_ATOMS * 128) g_p1scat[idx] = 0.0f;
    if (idx < N_ATOMS * 192) g_p3acc[idx] = 0.0f;
}

// ---------------- kernel 0b: reorder piW into [z][b][k][c] ----------------
__global__ void prep_kernel(const float* __restrict__ piW) {
    int idx = blockIdx.x * blockDim.x + threadIdx.x;
    if (idx >= 2 * 10 * 64 * 64) return;
    int c  = idx & 63;
    int k  = (idx >> 6) & 63;
    int zb = idx >> 12;          // z*10 + b
    int z  = zb / 10, b = zb % 10;
    g_piWn[idx] = piW[(z * 64 + k) * 640 + c * 10 + b];
}

// ---------------- kernel 1: p1_in = tanh(tanh(p1@W1+b1)@W2+b2) ----------------
__global__ void p1in_kernel(const float* __restrict__ p1,
                            const float* __restrict__ W1, const float* __restrict__ b1,
                            const float* __restrict__ W2, const float* __restrict__ b2) {
    __shared__ float W1s[4096], W2s[4096], b1s[64], b2s[64];
    __shared__ float xr[4 * 64], hs[4 * 64];
    int tid = threadIdx.x;
    for (int idx = tid; idx < 4096; idx += 256) { W1s[idx] = W1[idx]; W2s[idx] = W2[idx]; }
    if (tid < 64) { b1s[tid] = b1[tid]; b2s[tid] = b2[tid]; }
    int slot = tid >> 6, c = tid & 63;
    int a = blockIdx.x * 4 + slot;
    xr[slot * 64 + c] = p1[a * 64 + c];
    __syncthreads();
    float h = b1s[c];
    #pragma unroll 8
    for (int k = 0; k < 64; ++k) h += xr[slot * 64 + k] * W1s[k * 64 + c];
    hs[slot * 64 + c] = tanhf(h);
    __syncthreads();
    float o = b2s[c];
    #pragma unroll 8
    for (int k = 0; k < 64; ++k) o += hs[slot * 64 + k] * W2s[k * 64 + c];
    g_p1in[a * 64 + c] = tanhf(o);
}

// ---------------- kernel 1b: A/B builder  (grid: x=atom tiles, y=b, z=half) ----
__global__ __launch_bounds__(256) void ab_kernel(const float* __restrict__ pib) {
    __shared__ float Wb[4096];   // [k][c]
    __shared__ float xr[4 * 64];
    int tid = threadIdx.x;
    int b = blockIdx.y, z = blockIdx.z;
    for (int idx = tid; idx < 4096; idx += 256)
        Wb[idx] = g_piWn[(z * 10 + b) * 4096 + idx];
    int slot = tid >> 6, c = tid & 63;
    float bias = (z == 0) ? pib[c * 10 + b] : 0.0f;
    float* out = z ? g_B : g_A;
    for (int it = 0; it < 16; ++it) {
        int a = blockIdx.x * 64 + it * 4 + slot;
        __syncthreads();
        if (a < N_ATOMS) xr[slot * 64 + c] = g_p1in[a * 64 + c];
        __syncthreads();
        float s = bias;
        #pragma unroll 8
        for (int k = 0; k < 64; ++k) s += xr[slot * 64 + k] * Wb[k * 64 + c];
        if (a < N_ATOMS) out[(size_t)a * 640 + b * 64 + c] = s;
    }
}

// ---------------- kernel 2: v = segment_sum(d3*fc, i) ----------------
__global__ void vacc_kernel(const int* __restrict__ ind2,
                            const float* __restrict__ d3,
                            const float* __restrict__ fc) {
    int p = blockIdx.x * blockDim.x + threadIdx.x;
    if (p >= N_PAIRS) return;
    int i = ind2[2 * p];
    float f = fc[p];
    atomicAdd(&g_v[i * 3 + 0], d3[p * 3 + 0] * f);
    atomicAdd(&g_v[i * 3 + 1], d3[p * 3 + 1] * f);
    atomicAdd(&g_v[i * 3 + 2], d3[p * 3 + 2] * f);
}

// ---------------- kernel 3: main per-pair kernel ----------------
// 64 pairs/block, 256 threads (8 warps), 5000 blocks.
// smem (floats):
//   sIp [0, 4160)      64x65 i_pair
//   Z   [4160, 12416)  64x129
//   Ws  [12416, 20608) iiW 64x128
//   sB  [20608, 21248) basis 64x10
//   sD3 [21248, 21440) sFc [21440, 21504) sI/sJ [21504, 21632)
#define PAIR_SMEM_FLOATS 21632
__global__ __launch_bounds__(256, 2) void pair_kernel(
                            const int* __restrict__ ind2,
                            const float* __restrict__ p3,
                            const float* __restrict__ basis,
                            const float* __restrict__ d3,
                            const float* __restrict__ fc,
                            const float* __restrict__ iiW) {
    extern __shared__ float sm[];
    float* sIp   = sm;
    float* Z     = sm + 4160;
    float* Ws    = sm + 12416;
    float* sB    = sm + 20608;
    float* sD3   = sm + 21248;
    float* sFc   = sm + 21440;
    int*   sI    = (int*)(sm + 21504);
    int*   sJ    = sI + 64;

    int tid = threadIdx.x;
    int lane = tid & 31;
    int wg   = tid >> 5;
    int pbase = blockIdx.x * 64;

    if (tid < 64) {
        sI[tid]  = ind2[2 * (pbase + tid)];
        sJ[tid]  = ind2[2 * (pbase + tid) + 1];
        sFc[tid] = fc[pbase + tid];
    }
    for (int idx = tid; idx < 192; idx += 256) sD3[idx] = d3[pbase * 3 + idx];
    for (int idx = tid; idx < 640; idx += 256) sB[idx]  = basis[pbase * 10 + idx];
    for (int idx = tid; idx < 8192; idx += 256) Ws[idx] = iiW[idx];
    __syncthreads();

    // ---- stage 1: i_pair[m][c] = sum_b tanh(A[i][b*64+c] + B[j][b*64+c]) * basis[m][b]
    // warp wg handles pairs wg*8..wg*8+7; lane covers channels (2*lane, 2*lane+1)
    {
        int c2 = lane * 2;
        #pragma unroll 2
        for (int r = 0; r < 8; ++r) {
            int m = wg * 8 + r;
            const float2* Ai = (const float2*)(g_A + (size_t)sI[m] * 640) + lane;
            const float2* Bj = (const float2*)(g_B + (size_t)sJ[m] * 640) + lane;
            float2 av[10], bv[10];
            #pragma unroll
            for (int b = 0; b < 10; ++b) { av[b] = Ai[b * 32]; bv[b] = Bj[b * 32]; }
            float s0 = 0.0f, s1 = 0.0f;
            #pragma unroll
            for (int b = 0; b < 10; ++b) {
                float bas = sB[m * 10 + b];
                s0 += tanh_fast(av[b].x + bv[b].x) * bas;
                s1 += tanh_fast(av[b].y + bv[b].y) * bas;
            }
            sIp[m * 65 + c2]     = s0;
            sIp[m * 65 + c2 + 1] = s1;
        }
    }
    __syncthreads();

    // ---- stage 2: z = tanh(i_pair @ iiW)  (64 -> 128), into Z (stride 129) ----
    {
        int n0 = wg * 16;
        ull z0[8], z1[8];
        #pragma unroll
        for (int t = 0; t < 8; ++t) { z0[t] = 0ULL; z1[t] = 0ULL; }
        const float* ir0 = sIp + lane * 65;
        const float* ir1 = sIp + (lane + 32) * 65;
        #pragma unroll 4
        for (int k = 0; k < 64; ++k) {
            ull A0 = pack2(ir0[k]);
            ull A1 = pack2(ir1[k]);
            const ull* qp = (const ull*)(Ws + k * 128 + n0);
            #pragma unroll
            for (int t = 0; t < 8; ++t) {
                ull w = qp[t];
                fma2(z0[t], A0, w);
                fma2(z1[t], A1, w);
            }
        }
        float* zr0 = Z + lane * 129;
        float* zr1 = Z + (lane + 32) * 129;
        #pragma unroll
        for (int t = 0; t < 8; ++t) {
            float2 a = unpack2(z0[t]);
            float2 b = unpack2(z1[t]);
            zr0[n0 + 2 * t]     = tanh_fast(a.x);
            zr0[n0 + 2 * t + 1] = tanh_fast(a.y);
            zr1[n0 + 2 * t]     = tanh_fast(b.x);
            zr1[n0 + 2 * t + 1] = tanh_fast(b.y);
        }
    }
    __syncthreads();

    // ---- stage 3: scatter z; geometry; scatter ix ----
    {
        int m = tid >> 2, q = tid & 3;
        int i = sI[m], j = sJ[m];
        float fcv = sFc[m];
        float dx = sD3[m * 3 + 0], dy = sD3[m * 3 + 1], dz = sD3[m * 3 + 2];
        float vx = g_v[i * 3 + 0], vy = g_v[i * 3 + 1], vz = g_v[i * 3 + 2];
        float proj = vx * dx + vy * dy + vz * dz;
        float wx = vx - proj * dx, wy = vy - proj * dy, wzc = vz - proj * dz;
        float w2 = wx * wx + wy * wy + wzc * wzc;
        float gdeg = w2 / (w2 + 1e-4f);
        float rs = rsqrtf(w2 + 1e-6f);
        float sc = rs * gdeg;
        float t3x = wx * sc, t3y = wy * sc, t3z = wzc * sc;
        float tb = gdeg * fcv * fcv;

        const float* zr = Z + m * 129;
        float* ps = g_p1scat + (size_t)i * 128;
        #pragma unroll 8
        for (int t = 0; t < 32; ++t) atomicAdd(ps + q * 32 + t, zr[q * 32 + t]);

        const float* p3j = p3 + (size_t)j * 192;
        float* pa = g_p3acc + (size_t)i * 192;
        #pragma unroll 4
        for (int t = 0; t < 16; ++t) {
            int ccl = q * 16 + t;
            float g = zr[64 + ccl];
            float coef = g * tb;
            atomicAdd(pa + ccl,        p3j[ccl] * g        + dx * g + t3x * coef);
            atomicAdd(pa + 64 + ccl,   p3j[64 + ccl] * g   + dy * g + t3y * coef);
            atomicAdd(pa + 128 + ccl,  p3j[128 + ccl] * g  + dz * g + t3z * coef);
        }
    }
}

// ---------------- kernel 4: atom-side tail, writes d_out ----------------
#define FINAL_SMEM_FLOATS 36032
__global__ void atom_final_kernel(const float* __restrict__ postW1,
                                  const float* __restrict__ postW2,
                                  const float* __restrict__ eqW,
                                  const float* __restrict__ q1W,
                                  const float* __restrict__ q1b,
                                  const float* __restrict__ q2W,
                                  const float* __restrict__ q2b,
                                  float* __restrict__ out) {
    extern __shared__ float sm[];
    float* W1s  = sm;
    float* W2s  = sm + 8192;
    float* Es   = sm + 12288;
    float* Q1s  = sm + 16384;
    float* Q2s  = sm + 24576;
    float* b1s  = sm + 32768;
    float* b2s  = sm + 32832;
    float* ps   = sm + 32960;
    float* p3a  = sm + 33472;
    float* sH   = sm + 34240;
    float* sP1  = sm + 34496;
    float* sP3n = sm + 34752;
    float* sD   = sm + 35520;
    float* sH2  = sm + 35776;

    int tid = threadIdx.x;
    for (int idx = tid; idx < 8192; idx += 256) W1s[idx] = postW1[idx];
    for (int idx = tid; idx < 4096; idx += 256) { W2s[idx] = postW2[idx]; Es[idx] = eqW[idx]; }
    for (int idx = tid; idx < 8192; idx += 256) { Q1s[idx] = q1W[idx]; Q2s[idx] = q2W[idx]; }
    if (tid < 64)  b1s[tid] = q1b[tid];
    if (tid < 128) b2s[tid] = q2b[tid];

    int slot = tid >> 6, c = tid & 63;
    int abase = blockIdx.x * 68;
    for (int it = 0; it < 17; ++it) {
        __syncthreads();
        int a = abase + it * 4 + slot;
        bool valid = (a < N_ATOMS);
        if (valid) {
            ps[slot * 128 + c]       = g_p1scat[a * 128 + c];
            ps[slot * 128 + 64 + c]  = g_p1scat[a * 128 + 64 + c];
            p3a[slot * 192 + c]       = g_p3acc[a * 192 + c];
            p3a[slot * 192 + 64 + c]  = g_p3acc[a * 192 + 64 + c];
            p3a[slot * 192 + 128 + c] = g_p3acc[a * 192 + 128 + c];
        } else {
            ps[slot * 128 + c] = 0.0f; ps[slot * 128 + 64 + c] = 0.0f;
            p3a[slot * 192 + c] = 0.0f; p3a[slot * 192 + 64 + c] = 0.0f;
            p3a[slot * 192 + 128 + c] = 0.0f;
        }
        __syncthreads();
        float h = 0.0f;
        #pragma unroll 8
        for (int k = 0; k < 128; ++k) h += ps[slot * 128 + k] * W1s[k * 64 + c];
        sH[slot * 64 + c] = tanhf(h);
        __syncthreads();
        float o = 0.0f;
        float p0 = 0.0f, p1v = 0.0f, p2 = 0.0f;
        #pragma unroll 8
        for (int k = 0; k < 64; ++k) {
            o += sH[slot * 64 + k] * W2s[k * 64 + c];
            float e = Es[k * 64 + c];
            p0  += p3a[slot * 192 + k]       * e;
            p1v += p3a[slot * 192 + 64 + k]  * e;
            p2  += p3a[slot * 192 + 128 + k] * e;
        }
        sP1[slot * 64 + c] = tanhf(o);
        sP3n[slot * 192 + c]       = p0;
        sP3n[slot * 192 + 64 + c]  = p1v;
        sP3n[slot * 192 + 128 + c] = p2;
        sD[slot * 64 + c] = p0 * p0 + p1v * p1v + p2 * p2;
        __syncthreads();
        float h2 = b1s[c];
        #pragma unroll 8
        for (int k = 0; k < 64; ++k) {
            h2 += sP1[slot * 64 + k] * Q1s[k * 64 + c];
            h2 += sD[slot * 64 + k]  * Q1s[(64 + k) * 64 + c];
        }
        sH2[slot * 64 + c] = tanhf(h2);
        __syncthreads();
        float o1 = b2s[c], o2 = b2s[64 + c];
        #pragma unroll 8
        for (int k = 0; k < 64; ++k) {
            float hh = sH2[slot * 64 + k];
            o1 += hh * Q2s[k * 128 + c];
            o2 += hh * Q2s[k * 128 + 64 + c];
        }
        o1 = tanhf(o1);
        o2 = tanhf(o2);
        if (valid) {
            out[a * 64 + c] = o1;
            float* po = out + N_ATOMS * 64 + (size_t)a * 192;
            po[c]        = sP3n[slot * 192 + c]       * o2;
            po[64 + c]   = sP3n[slot * 192 + 64 + c]  * o2;
            po[128 + c]  = sP3n[slot * 192 + 128 + c] * o2;
        }
    }
}

// ---------------- launch ----------------
extern "C" void kernel_launch(void* const* d_in, const int* in_sizes, int n_in,
                              void* d_out, int out_size) {
    const int*   ind2   = (const int*)d_in[0];
    const float* p1     = (const float*)d_in[1];
    const float* p3     = (const float*)d_in[2];
    const float* basis  = (const float*)d_in[3];
    const float* d3     = (const float*)d_in[4];
    const float* fc     = (const float*)d_in[5];
    const float* preW1  = (const float*)d_in[6];
    const float* preb1  = (const float*)d_in[7];
    const float* preW2  = (const float*)d_in[8];
    const float* preb2  = (const float*)d_in[9];
    const float* piW    = (const float*)d_in[10];
    const float* pib    = (const float*)d_in[11];
    const float* iiW    = (const float*)d_in[12];
    const float* postW1 = (const float*)d_in[13];
    const float* postW2 = (const float*)d_in[14];
    const float* eqW    = (const float*)d_in[15];
    const float* q1W    = (const float*)d_in[16];
    const float* q1b    = (const float*)d_in[17];
    const float* q2W    = (const float*)d_in[18];
    const float* q2b    = (const float*)d_in[19];
    float* out = (float*)d_out;

    cudaFuncSetAttribute(pair_kernel, cudaFuncAttributeMaxDynamicSharedMemorySize,
                         PAIR_SMEM_FLOATS * 4);
    cudaFuncSetAttribute(atom_final_kernel, cudaFuncAttributeMaxDynamicSharedMemorySize,
                         FINAL_SMEM_FLOATS * 4);

    zero_kernel<<<(N_ATOMS * 192 + 255) / 256, 256>>>();
    prep_kernel<<<(2 * 10 * 64 * 64 + 255) / 256, 256>>>(piW);
    p1in_kernel<<<N_ATOMS / 4, 256>>>(p1, preW1, preb1, preW2, preb2);
    {
        dim3 g((N_ATOMS + 63) / 64, 10, 2);
        ab_kernel<<<g, 256>>>(pib);
    }
    vacc_kernel<<<(N_PAIRS + 255) / 256, 256>>>(ind2, d3, fc);
    pair_kernel<<<N_PAIRS / 64, 256, PAIR_SMEM_FLOATS * 4>>>(ind2, p3, basis, d3, fc, iiW);
    atom_final_kernel<<<148, 256, FINAL_SMEM_FLOATS * 4>>>(postW1, postW2, eqW,
                                                           q1W, q1b, q2W, q2b, out);
}

// round 8
// speedup vs baseline: 4.5956x; 1.7443x over previous
#include <cuda_runtime.h>
#include <math.h>

#define N_ATOMS 10000
#define N_PAIRS 320000
#define CC 64

typedef unsigned long long ull;

// ---------------- f32x2 helpers (Blackwell packed fp32) ----------------
__device__ __forceinline__ ull pack2(float x) {
    ull r; asm("mov.b64 %0, {%1, %1};" : "=l"(r) : "f"(x)); return r;
}
__device__ __forceinline__ ull pack_pair(float lo, float hi) {
    ull r; asm("mov.b64 %0, {%1, %2};" : "=l"(r) : "f"(lo), "f"(hi)); return r;
}
__device__ __forceinline__ void fma2(ull& acc, ull a, ull b) {
    asm("fma.rn.f32x2 %0, %1, %2, %0;" : "+l"(acc) : "l"(a), "l"(b));
}
__device__ __forceinline__ float2 unpack2(ull v) {
    float2 f; asm("mov.b64 {%0, %1}, %2;" : "=f"(f.x), "=f"(f.y) : "l"(v)); return f;
}
__device__ __forceinline__ float tanh_fast(float x) {
    float y; asm("tanh.approx.f32 %0, %1;" : "=f"(y) : "f"(x)); return y;
}
__device__ __forceinline__ void red_add_v4(float* addr, float a, float b, float c, float d) {
    asm volatile("red.global.add.v4.f32 [%0], {%1, %2, %3, %4};"
                 :: "l"(addr), "f"(a), "f"(b), "f"(c), "f"(d) : "memory");
}

// ---------------- scratch (device globals; no allocation allowed) ----------------
__device__ float g_p1in[N_ATOMS * 64];
__device__ float g_v[N_ATOMS * 3];
__device__ float g_p1scat[N_ATOMS * 128];
__device__ float g_p3acc[N_ATOMS * 192];
__device__ float g_piWn[2 * 10 * 64 * 64];   // [z][b][k][c]
__device__ float g_A[N_ATOMS * 640];         // p1in @ Wtop + pib   [atom][b][c]
__device__ float g_B[N_ATOMS * 640];         // p1in @ Wbot         [atom][b][c]

// ---------------- kernel 0: zero scratch ----------------
__global__ void zero_kernel() {
    int idx = blockIdx.x * blockDim.x + threadIdx.x;
    if (idx < N_ATOMS * 3)   g_v[idx] = 0.0f;
    if (idx < N_ATOMS * 128) g_p1scat[idx] = 0.0f;
    if (idx < N_ATOMS * 192) g_p3acc[idx] = 0.0f;
}

// ---------------- kernel 0b: reorder piW into [z][b][k][c] ----------------
__global__ void prep_kernel(const float* __restrict__ piW) {
    int idx = blockIdx.x * blockDim.x + threadIdx.x;
    if (idx >= 2 * 10 * 64 * 64) return;
    int c  = idx & 63;
    int k  = (idx >> 6) & 63;
    int zb = idx >> 12;
    int z  = zb / 10, b = zb % 10;
    g_piWn[idx] = piW[(z * 64 + k) * 640 + c * 10 + b];
}

// ---------------- kernel 1: p1_in = tanh(tanh(p1@W1+b1)@W2+b2) ----------------
__global__ void p1in_kernel(const float* __restrict__ p1,
                            const float* __restrict__ W1, const float* __restrict__ b1,
                            const float* __restrict__ W2, const float* __restrict__ b2) {
    __shared__ float W1s[4096], W2s[4096], b1s[64], b2s[64];
    __shared__ float xr[4 * 64], hs[4 * 64];
    int tid = threadIdx.x;
    for (int idx = tid; idx < 4096; idx += 256) { W1s[idx] = W1[idx]; W2s[idx] = W2[idx]; }
    if (tid < 64) { b1s[tid] = b1[tid]; b2s[tid] = b2[tid]; }
    int slot = tid >> 6, c = tid & 63;
    int a = blockIdx.x * 4 + slot;
    xr[slot * 64 + c] = p1[a * 64 + c];
    __syncthreads();
    float h = b1s[c];
    #pragma unroll 8
    for (int k = 0; k < 64; ++k) h += xr[slot * 64 + k] * W1s[k * 64 + c];
    hs[slot * 64 + c] = tanhf(h);
    __syncthreads();
    float o = b2s[c];
    #pragma unroll 8
    for (int k = 0; k < 64; ++k) o += hs[slot * 64 + k] * W2s[k * 64 + c];
    g_p1in[a * 64 + c] = tanhf(o);
}

// ---------------- kernel 1b: A/B builder — f32x2 GEMM ----------------
// grid (157, 20): y = z*10+b chunk. Block: 64 atoms x 64 channels.
// warp wg -> atoms wg*8..wg*8+7 (broadcast), lane -> channel pair (2l, 2l+1).
__global__ __launch_bounds__(256) void ab_kernel(const float* __restrict__ pib) {
    __shared__ float xs[64 * 68];   // [k][atom], stride 68 (16B-aligned f4 reads)
    __shared__ float Wb[4096];      // [k][c]
    int tid = threadIdx.x;
    int zb = blockIdx.y, z = zb / 10, b = zb % 10;
    int abase = blockIdx.x * 64;

    for (int idx = tid; idx < 4096; idx += 256) Wb[idx] = g_piWn[zb * 4096 + idx];
    {
        int k = tid & 63, a0 = tid >> 6;
        #pragma unroll 4
        for (int r = 0; r < 16; ++r) {
            int a = a0 + r * 4;
            int ga = abase + a;
            xs[k * 68 + a] = (ga < N_ATOMS) ? g_p1in[ga * 64 + k] : 0.0f;
        }
    }
    __syncthreads();

    int lane = tid & 31, wg = tid >> 5;
    int c2 = 2 * lane;
    ull bias = 0ULL;
    if (z == 0) bias = pack_pair(pib[c2 * 10 + b], pib[(c2 + 1) * 10 + b]);
    ull acc[8];
    #pragma unroll
    for (int r = 0; r < 8; ++r) acc[r] = bias;

    const ull* WbU = (const ull*)Wb;
    const float* xw = xs + wg * 8;
    #pragma unroll 4
    for (int k = 0; k < 64; ++k) {
        float4 x0 = *(const float4*)(xw + k * 68);
        float4 x1 = *(const float4*)(xw + k * 68 + 4);
        ull w = WbU[k * 32 + lane];
        fma2(acc[0], pack2(x0.x), w);
        fma2(acc[1], pack2(x0.y), w);
        fma2(acc[2], pack2(x0.z), w);
        fma2(acc[3], pack2(x0.w), w);
        fma2(acc[4], pack2(x1.x), w);
        fma2(acc[5], pack2(x1.y), w);
        fma2(acc[6], pack2(x1.z), w);
        fma2(acc[7], pack2(x1.w), w);
    }

    float* out = z ? g_B : g_A;
    #pragma unroll
    for (int r = 0; r < 8; ++r) {
        int a = abase + wg * 8 + r;
        if (a < N_ATOMS) {
            float2 v = unpack2(acc[r]);
            *(float2*)(out + (size_t)a * 640 + b * 64 + c2) = v;
        }
    }
}

// ---------------- kernel 2: v = segment_sum(d3*fc, i) ----------------
__global__ void vacc_kernel(const int* __restrict__ ind2,
                            const float* __restrict__ d3,
                            const float* __restrict__ fc) {
    int p = blockIdx.x * blockDim.x + threadIdx.x;
    if (p >= N_PAIRS) return;
    int i = ind2[2 * p];
    float f = fc[p];
    atomicAdd(&g_v[i * 3 + 0], d3[p * 3 + 0] * f);
    atomicAdd(&g_v[i * 3 + 1], d3[p * 3 + 1] * f);
    atomicAdd(&g_v[i * 3 + 2], d3[p * 3 + 2] * f);
}

// ---------------- kernel 3: main per-pair kernel ----------------
#define PAIR_SMEM_FLOATS 21632
__global__ __launch_bounds__(256, 2) void pair_kernel(
                            const int* __restrict__ ind2,
                            const float* __restrict__ p3,
                            const float* __restrict__ basis,
                            const float* __restrict__ d3,
                            const float* __restrict__ fc,
                            const float* __restrict__ iiW) {
    extern __shared__ float sm[];
    float* sIp   = sm;
    float* Z     = sm + 4160;
    float* Ws    = sm + 12416;
    float* sB    = sm + 20608;
    float* sD3   = sm + 21248;
    float* sFc   = sm + 21440;
    int*   sI    = (int*)(sm + 21504);
    int*   sJ    = sI + 64;

    int tid = threadIdx.x;
    int lane = tid & 31;
    int wg   = tid >> 5;
    int pbase = blockIdx.x * 64;

    if (tid < 64) {
        sI[tid]  = ind2[2 * (pbase + tid)];
        sJ[tid]  = ind2[2 * (pbase + tid) + 1];
        sFc[tid] = fc[pbase + tid];
    }
    for (int idx = tid; idx < 192; idx += 256) sD3[idx] = d3[pbase * 3 + idx];
    for (int idx = tid; idx < 640; idx += 256) sB[idx]  = basis[pbase * 10 + idx];
    for (int idx = tid; idx < 8192; idx += 256) Ws[idx] = iiW[idx];
    __syncthreads();

    // ---- stage 1: i_pair[m][c] = sum_b tanh(A[i][b*64+c] + B[j][b*64+c]) * basis[m][b]
    {
        int c2 = lane * 2;
        #pragma unroll 2
        for (int r = 0; r < 8; ++r) {
            int m = wg * 8 + r;
            const float2* Ai = (const float2*)(g_A + (size_t)sI[m] * 640) + lane;
            const float2* Bj = (const float2*)(g_B + (size_t)sJ[m] * 640) + lane;
            float2 av[10], bv[10];
            #pragma unroll
            for (int b = 0; b < 10; ++b) { av[b] = Ai[b * 32]; bv[b] = Bj[b * 32]; }
            float s0 = 0.0f, s1 = 0.0f;
            #pragma unroll
            for (int b = 0; b < 10; ++b) {
                float bas = sB[m * 10 + b];
                s0 += tanh_fast(av[b].x + bv[b].x) * bas;
                s1 += tanh_fast(av[b].y + bv[b].y) * bas;
            }
            sIp[m * 65 + c2]     = s0;
            sIp[m * 65 + c2 + 1] = s1;
        }
    }
    __syncthreads();

    // ---- stage 2: z = tanh(i_pair @ iiW)  (64 -> 128), into Z (stride 129) ----
    {
        int n0 = wg * 16;
        ull z0[8], z1[8];
        #pragma unroll
        for (int t = 0; t < 8; ++t) { z0[t] = 0ULL; z1[t] = 0ULL; }
        const float* ir0 = sIp + lane * 65;
        const float* ir1 = sIp + (lane + 32) * 65;
        #pragma unroll 4
        for (int k = 0; k < 64; ++k) {
            ull A0 = pack2(ir0[k]);
            ull A1 = pack2(ir1[k]);
            const ull* qp = (const ull*)(Ws + k * 128 + n0);
            #pragma unroll
            for (int t = 0; t < 8; ++t) {
                ull w = qp[t];
                fma2(z0[t], A0, w);
                fma2(z1[t], A1, w);
            }
        }
        float* zr0 = Z + lane * 129;
        float* zr1 = Z + (lane + 32) * 129;
        #pragma unroll
        for (int t = 0; t < 8; ++t) {
            float2 a = unpack2(z0[t]);
            float2 b = unpack2(z1[t]);
            zr0[n0 + 2 * t]     = tanh_fast(a.x);
            zr0[n0 + 2 * t + 1] = tanh_fast(a.y);
            zr1[n0 + 2 * t]     = tanh_fast(b.x);
            zr1[n0 + 2 * t + 1] = tanh_fast(b.y);
        }
    }
    __syncthreads();

    // ---- stage 3: scatter z (v4 red); geometry; scatter ix (v4 red) ----
    {
        int m = tid >> 2, q = tid & 3;
        int i = sI[m], j = sJ[m];
        float fcv = sFc[m];
        float dx = sD3[m * 3 + 0], dy = sD3[m * 3 + 1], dz = sD3[m * 3 + 2];
        float vx = g_v[i * 3 + 0], vy = g_v[i * 3 + 1], vz = g_v[i * 3 + 2];
        float proj = vx * dx + vy * dy + vz * dz;
        float wx = vx - proj * dx, wy = vy - proj * dy, wzc = vz - proj * dz;
        float w2 = wx * wx + wy * wy + wzc * wzc;
        float gdeg = w2 / (w2 + 1e-4f);
        float rs = rsqrtf(w2 + 1e-6f);
        float sc = rs * gdeg;
        float t3x = wx * sc, t3y = wy * sc, t3z = wzc * sc;
        float tb = gdeg * fcv * fcv;

        const float* zr = Z + m * 129;
        float* ps = g_p1scat + (size_t)i * 128 + q * 32;
        const float* z1p = zr + q * 32;
        #pragma unroll
        for (int t = 0; t < 8; ++t)
            red_add_v4(ps + 4 * t, z1p[4 * t], z1p[4 * t + 1], z1p[4 * t + 2], z1p[4 * t + 3]);

        const float* p3j = p3 + (size_t)j * 192;
        float* pa = g_p3acc + (size_t)i * 192;
        #pragma unroll
        for (int t4 = 0; t4 < 4; ++t4) {
            int c0 = q * 16 + 4 * t4;
            float g0 = zr[64 + c0], g1 = zr[64 + c0 + 1], g2 = zr[64 + c0 + 2], g3 = zr[64 + c0 + 3];
            float k0 = g0 * tb, k1 = g1 * tb, k2 = g2 * tb, k3 = g3 * tb;
            float4 px = *(const float4*)(p3j + c0);
            float4 py = *(const float4*)(p3j + 64 + c0);
            float4 pz = *(const float4*)(p3j + 128 + c0);
            red_add_v4(pa + c0,
                       px.x * g0 + dx * g0 + t3x * k0,
                       px.y * g1 + dx * g1 + t3x * k1,
                       px.z * g2 + dx * g2 + t3x * k2,
                       px.w * g3 + dx * g3 + t3x * k3);
            red_add_v4(pa + 64 + c0,
                       py.x * g0 + dy * g0 + t3y * k0,
                       py.y * g1 + dy * g1 + t3y * k1,
                       py.z * g2 + dy * g2 + t3y * k2,
                       py.w * g3 + dy * g3 + t3y * k3);
            red_add_v4(pa + 128 + c0,
                       pz.x * g0 + dz * g0 + t3z * k0,
                       pz.y * g1 + dz * g1 + t3z * k1,
                       pz.z * g2 + dz * g2 + t3z * k2,
                       pz.w * g3 + dz * g3 + t3z * k3);
        }
    }
}

// ---------------- kernel 4: atom-side tail, writes d_out ----------------
#define FINAL_SMEM_FLOATS 36032
__global__ void atom_final_kernel(const float* __restrict__ postW1,
                                  const float* __restrict__ postW2,
                                  const float* __restrict__ eqW,
                                  const float* __restrict__ q1W,
                                  const float* __restrict__ q1b,
                                  const float* __restrict__ q2W,
                                  const float* __restrict__ q2b,
                                  float* __restrict__ out) {
    extern __shared__ float sm[];
    float* W1s  = sm;
    float* W2s  = sm + 8192;
    float* Es   = sm + 12288;
    float* Q1s  = sm + 16384;
    float* Q2s  = sm + 24576;
    float* b1s  = sm + 32768;
    float* b2s  = sm + 32832;
    float* ps   = sm + 32960;
    float* p3a  = sm + 33472;
    float* sH   = sm + 34240;
    float* sP1  = sm + 34496;
    float* sP3n = sm + 34752;
    float* sD   = sm + 35520;
    float* sH2  = sm + 35776;

    int tid = threadIdx.x;
    for (int idx = tid; idx < 8192; idx += 256) W1s[idx] = postW1[idx];
    for (int idx = tid; idx < 4096; idx += 256) { W2s[idx] = postW2[idx]; Es[idx] = eqW[idx]; }
    for (int idx = tid; idx < 8192; idx += 256) { Q1s[idx] = q1W[idx]; Q2s[idx] = q2W[idx]; }
    if (tid < 64)  b1s[tid] = q1b[tid];
    if (tid < 128) b2s[tid] = q2b[tid];

    int slot = tid >> 6, c = tid & 63;
    int abase = blockIdx.x * 68;
    for (int it = 0; it < 17; ++it) {
        __syncthreads();
        int a = abase + it * 4 + slot;
        bool valid = (a < N_ATOMS);
        if (valid) {
            ps[slot * 128 + c]       = g_p1scat[a * 128 + c];
            ps[slot * 128 + 64 + c]  = g_p1scat[a * 128 + 64 + c];
            p3a[slot * 192 + c]       = g_p3acc[a * 192 + c];
            p3a[slot * 192 + 64 + c]  = g_p3acc[a * 192 + 64 + c];
            p3a[slot * 192 + 128 + c] = g_p3acc[a * 192 + 128 + c];
        } else {
            ps[slot * 128 + c] = 0.0f; ps[slot * 128 + 64 + c] = 0.0f;
            p3a[slot * 192 + c] = 0.0f; p3a[slot * 192 + 64 + c] = 0.0f;
            p3a[slot * 192 + 128 + c] = 0.0f;
        }
        __syncthreads();
        float h = 0.0f;
        #pragma unroll 8
        for (int k = 0; k < 128; ++k) h += ps[slot * 128 + k] * W1s[k * 64 + c];
        sH[slot * 64 + c] = tanhf(h);
        __syncthreads();
        float o = 0.0f;
        float p0 = 0.0f, p1v = 0.0f, p2 = 0.0f;
        #pragma unroll 8
        for (int k = 0; k < 64; ++k) {
            o += sH[slot * 64 + k] * W2s[k * 64 + c];
            float e = Es[k * 64 + c];
            p0  += p3a[slot * 192 + k]       * e;
            p1v += p3a[slot * 192 + 64 + k]  * e;
            p2  += p3a[slot * 192 + 128 + k] * e;
        }
        sP1[slot * 64 + c] = tanhf(o);
        sP3n[slot * 192 + c]       = p0;
        sP3n[slot * 192 + 64 + c]  = p1v;
        sP3n[slot * 192 + 128 + c] = p2;
        sD[slot * 64 + c] = p0 * p0 + p1v * p1v + p2 * p2;
        __syncthreads();
        float h2 = b1s[c];
        #pragma unroll 8
        for (int k = 0; k < 64; ++k) {
            h2 += sP1[slot * 64 + k] * Q1s[k * 64 + c];
            h2 += sD[slot * 64 + k]  * Q1s[(64 + k) * 64 + c];
        }
        sH2[slot * 64 + c] = tanhf(h2);
        __syncthreads();
        float o1 = b2s[c], o2 = b2s[64 + c];
        #pragma unroll 8
        for (int k = 0; k < 64; ++k) {
            float hh = sH2[slot * 64 + k];
            o1 += hh * Q2s[k * 128 + c];
            o2 += hh * Q2s[k * 128 + 64 + c];
        }
        o1 = tanhf(o1);
        o2 = tanhf(o2);
        if (valid) {
            out[a * 64 + c] = o1;
            float* po = out + N_ATOMS * 64 + (size_t)a * 192;
            po[c]        = sP3n[slot * 192 + c]       * o2;
            po[64 + c]   = sP3n[slot * 192 + 64 + c]  * o2;
            po[128 + c]  = sP3n[slot * 192 + 128 + c] * o2;
        }
    }
}

// ---------------- launch ----------------
extern "C" void kernel_launch(void* const* d_in, const int* in_sizes, int n_in,
                              void* d_out, int out_size) {
    const int*   ind2   = (const int*)d_in[0];
    const float* p1     = (const float*)d_in[1];
    const float* p3     = (const float*)d_in[2];
    const float* basis  = (const float*)d_in[3];
    const float* d3     = (const float*)d_in[4];
    const float* fc     = (const float*)d_in[5];
    const float* preW1  = (const float*)d_in[6];
    const float* preb1  = (const float*)d_in[7];
    const float* preW2  = (const float*)d_in[8];
    const float* preb2  = (const float*)d_in[9];
    const float* piW    = (const float*)d_in[10];
    const float* pib    = (const float*)d_in[11];
    const float* iiW    = (const float*)d_in[12];
    const float* postW1 = (const float*)d_in[13];
    const float* postW2 = (const float*)d_in[14];
    const float* eqW    = (const float*)d_in[15];
    const float* q1W    = (const float*)d_in[16];
    const float* q1b    = (const float*)d_in[17];
    const float* q2W    = (const float*)d_in[18];
    const float* q2b    = (const float*)d_in[19];
    float* out = (float*)d_out;

    cudaFuncSetAttribute(pair_kernel, cudaFuncAttributeMaxDynamicSharedMemorySize,
                         PAIR_SMEM_FLOATS * 4);
    cudaFuncSetAttribute(atom_final_kernel, cudaFuncAttributeMaxDynamicSharedMemorySize,
                         FINAL_SMEM_FLOATS * 4);

    zero_kernel<<<(N_ATOMS * 192 + 255) / 256, 256>>>();
    prep_kernel<<<(2 * 10 * 64 * 64 + 255) / 256, 256>>>(piW);
    p1in_kernel<<<N_ATOMS / 4, 256>>>(p1, preW1, preb1, preW2, preb2);
    {
        dim3 g((N_ATOMS + 63) / 64, 20, 1);
        ab_kernel<<<g, 256>>>(pib);
    }
    vacc_kernel<<<(N_PAIRS + 255) / 256, 256>>>(ind2, d3, fc);
    pair_kernel<<<N_PAIRS / 64, 256, PAIR_SMEM_FLOATS * 4>>>(ind2, p3, basis, d3, fc, iiW);
    atom_final_kernel<<<148, 256, FINAL_SMEM_FLOATS * 4>>>(postW1, postW2, eqW,
                                                           q1W, q1b, q2W, q2b, out);
}